// round 13
// baseline (speedup 1.0000x reference)
#include <cuda_runtime.h>
#include <cstddef>
#include <cstdint>

#define NEGV -1000000000.0f
#define HDIM 128
#define NMAX 12288
#define N_PART_BLKS 384
#define CHUNK_F4   1024          // float4s per output chunk (16KB)
#define CHUNK_FL   4096          // floats per chunk
#define NCHUNKS    36864         // (12288*12288/4096)
#define CAP        64            // max edges per chunk (Poisson mean 10.7)

__device__ float2 g_p[NMAX];                 // per-node partials
__device__ int    g_cnt[NCHUNKS];            // per-chunk edge count (zero invariant)
__device__ uint4  g_bucket[NCHUNKS * CAP];   // {flat addr, src, dest, weight bits}

// K1: partials blocks + binning blocks. Roles touch disjoint state -> no ordering.
__global__ void __launch_bounds__(256)
k1_part_bin(const float* __restrict__ h,
            const int* __restrict__ sources,
            const int* __restrict__ dests,
            const float* __restrict__ weights,
            const float* __restrict__ W,
            int N, int E) {
    const int tid = threadIdx.x;
    const int bid = blockIdx.x;

    if (bid < N_PART_BLKS) {
        // partials: 8 lanes/node, 4 nodes/warp, 32 nodes/block
        const int warp = tid >> 5;
        const int lane = tid & 31;
        const int sub  = lane & 7;
        const int grp  = lane >> 3;
        const int node = bid * 32 + warp * 4 + grp;
        if (node < N) {
            const float* hp = h + (size_t)node * HDIM + sub * 16;
            const float* wp = W + sub * 16;
            float ad = 0.0f, as = 0.0f;
            #pragma unroll
            for (int k = 0; k < 4; k++) {
                const float4 hv = *reinterpret_cast<const float4*>(hp + k * 4);
                const float4 wd = *reinterpret_cast<const float4*>(wp + k * 4);
                const float4 ws = *reinterpret_cast<const float4*>(wp + HDIM + k * 4);
                ad += hv.x * wd.x + hv.y * wd.y + hv.z * wd.z + hv.w * wd.w;
                as += hv.x * ws.x + hv.y * ws.y + hv.z * ws.z + hv.w * ws.w;
            }
            #pragma unroll
            for (int o = 4; o; o >>= 1) {
                ad += __shfl_xor_sync(0xffffffffu, ad, o);
                as += __shfl_xor_sync(0xffffffffu, as, o);
            }
            if (sub == 0) g_p[node] = make_float2(ad, as);
        }
    } else {
        // binning: one edge per thread -> bucket of its 4096-float chunk
        const int e = (bid - N_PART_BLKS) * 256 + tid;
        if (e < E) {
            const int s = sources[e];
            const int d = dests[e];
            const float w = weights[e];
            const uint32_t addr = (uint32_t)d * (uint32_t)N + (uint32_t)s;
            const uint32_t c = addr >> 12;          // /4096
            int slot = atomicAdd(&g_cnt[c], 1);
            if (slot < CAP) {
                g_bucket[c * CAP + slot] =
                    make_uint4(addr, (uint32_t)s, (uint32_t)d, __float_as_uint(w));
            }
        }
    }
}

// K2: one block per 16KB chunk. Compose chunk (NEG + edge patches) in smem,
// then stream it out with the proven coalesced float4 pattern. No post-store
// barrier -> no store-drain stall (the R8 failure mode).
__global__ void __launch_bounds__(256)
k2_fill_patch(const float* __restrict__ W,
              const float* __restrict__ b,
              float4* __restrict__ out) {
    const int c   = blockIdx.x;
    const int tid = threadIdx.x;

    __shared__ __align__(16) float s_patch[CHUNK_FL];
    __shared__ int s_cnt;

    if (tid == 0) {
        int cc = g_cnt[c];
        g_cnt[c] = 0;                     // restore zero invariant for next replay
        s_cnt = (cc < CAP) ? cc : CAP;
    }
    float4* sp4 = reinterpret_cast<float4*>(s_patch);
    const float4 v = make_float4(NEGV, NEGV, NEGV, NEGV);
    #pragma unroll
    for (int k = 0; k < 4; k++) {
        sp4[tid + k * 256] = v;
    }
    __syncthreads();

    if (tid < s_cnt) {
        const uint4 eb = g_bucket[c * CAP + tid];
        const float val = __ldg(&g_p[eb.z]).x + __ldg(&g_p[eb.y]).y
                        + __uint_as_float(eb.w) * __ldg(W + 2 * HDIM) + __ldg(b);
        s_patch[eb.x & (CHUNK_FL - 1)] = val;
    }
    __syncthreads();   // waits only on ~11 L2 gathers, NOT on global stores

    float4* dst = out + (size_t)c * CHUNK_F4;
    #pragma unroll
    for (int k = 0; k < 4; k++) {
        const int i = tid + k * 256;
        dst[i] = sp4[i];
    }
}

extern "C" void kernel_launch(void* const* d_in, const int* in_sizes, int n_in,
                              void* d_out, int out_size) {
    const float* h       = (const float*)d_in[0];
    const int*   sources = (const int*)d_in[1];
    const int*   dests   = (const int*)d_in[2];
    const float* weights = (const float*)d_in[3];
    const float* W       = (const float*)d_in[4];
    const float* b       = (const float*)d_in[5];
    float* out = (float*)d_out;

    const int N = in_sizes[0] / HDIM;     // 12288
    const int E = in_sizes[1];            // 393216

    const int nBinBlks = (E + 255) / 256;             // 1536

    // K1: partials + binning (independent roles)
    k1_part_bin<<<N_PART_BLKS + nBinBlks, 256>>>(h, sources, dests, weights,
                                                 W, N, E);

    // K2: compose-and-stream every 16KB chunk (fill + patch fused, zero extra DRAM)
    k2_fill_patch<<<NCHUNKS, 256>>>(W, b, (float4*)out);
}

// round 14
// speedup vs baseline: 2.3095x; 2.3095x over previous
#include <cuda_runtime.h>
#include <cstddef>
#include <cstdint>

#define NEGV -1000000000.0f
#define HDIM 128
#define NMAX 12288
#define EMAX 393216
#define N_PART_BLKS 384
#define N_VALS_BLKS 192
#define SIDE_BLKS   (N_PART_BLKS + N_VALS_BLKS)

__device__ float2   g_p[NMAX];     // per-node partials
__device__ uint2    g_pack[EMAX];  // per-edge {flat index, value bits}
__device__ unsigned g_arrive;      // partials arrivals (self-reset each call)
__device__ unsigned g_pass;        // vals blocks past the spin (self-reset)

__device__ __forceinline__ void pdl_trigger() {
    asm volatile("griddepcontrol.launch_dependents;" ::: "memory");
}
__device__ __forceinline__ void pdl_wait() {
    asm volatile("griddepcontrol.wait;" ::: "memory");
}

// K2: three independent-progress roles in one grid.
//  - partials blocks: compute g_p, release-arrive on g_arrive
//  - vals blocks: spin for partials only (never for fill), pack edge results,
//                 last one self-resets the counters for the next graph replay
//  - fill blocks: pure immediate float4 stores (the 6.98 TB/s path, untouched)
__global__ void __launch_bounds__(256)
k2_fused(const float* __restrict__ h,
         const int* __restrict__ sources,
         const int* __restrict__ dests,
         const float* __restrict__ weights,
         const float* __restrict__ W,
         const float* __restrict__ b,
         float4* __restrict__ out,
         int N, int E, int n4) {
    pdl_trigger();
    const int tid = threadIdx.x;
    const int bid = blockIdx.x;

    if (bid < N_PART_BLKS) {
        // ---- partials: 8 lanes/node, 4 nodes/warp, 32 nodes/block
        const int warp = tid >> 5;
        const int lane = tid & 31;
        const int sub  = lane & 7;
        const int grp  = lane >> 3;
        const int node = bid * 32 + warp * 4 + grp;
        if (node < N) {
            const float* hp = h + (size_t)node * HDIM + sub * 16;
            const float* wp = W + sub * 16;
            float ad = 0.0f, as = 0.0f;
            #pragma unroll
            for (int k = 0; k < 4; k++) {
                const float4 hv = *reinterpret_cast<const float4*>(hp + k * 4);
                const float4 wd = *reinterpret_cast<const float4*>(wp + k * 4);
                const float4 ws = *reinterpret_cast<const float4*>(wp + HDIM + k * 4);
                ad += hv.x * wd.x + hv.y * wd.y + hv.z * wd.z + hv.w * wd.w;
                as += hv.x * ws.x + hv.y * ws.y + hv.z * ws.z + hv.w * ws.w;
            }
            #pragma unroll
            for (int o = 4; o; o >>= 1) {
                ad += __shfl_xor_sync(0xffffffffu, ad, o);
                as += __shfl_xor_sync(0xffffffffu, as, o);
            }
            if (sub == 0) g_p[node] = make_float2(ad, as);
        }
        __syncthreads();
        if (tid == 0) {
            __threadfence();                       // release g_p
            atomicAdd(&g_arrive, 1u);
        }
    } else if (bid < SIDE_BLKS) {
        // ---- vals: wait for all partials blocks, then pack edge results
        if (tid == 0) {
            volatile unsigned* ap = &g_arrive;
            while (*ap < (unsigned)N_PART_BLKS) __nanosleep(64);
        }
        __syncthreads();
        __threadfence();                           // acquire g_p

        const int vbid = bid - N_PART_BLKS;
        const float wW = __ldg(W + 2 * HDIM);
        const float bb = __ldg(b);
        const int stride = N_VALS_BLKS * 256;
        for (int e = vbid * 256 + tid; e < E; e += stride) {
            const int s = sources[e];
            const int d = dests[e];
            const float2 pd = __ldg(&g_p[d]);
            const float2 ps = __ldg(&g_p[s]);
            const float val = pd.x + ps.y + weights[e] * wW + bb;
            g_pack[e] = make_uint2((uint32_t)d * (uint32_t)N + (uint32_t)s,
                                   __float_as_uint(val));
        }

        // self-reset: every vals block has passed the spin before the last
        // one arrives here, so zeroing the counters cannot strand a spinner.
        __syncthreads();
        if (tid == 0) {
            unsigned t = atomicAdd(&g_pass, 1u);
            if (t == N_VALS_BLKS - 1u) {
                g_pass = 0u;
                __threadfence();
                g_arrive = 0u;                     // invariant restored for next replay
            }
        }
    } else {
        // ---- fill: immediate-value float4 stores only (never touched by loads)
        const int fbid = bid - SIDE_BLKS;
        const float4 v = make_float4(NEGV, NEGV, NEGV, NEGV);
        const int base = fbid * 1024 + tid;
        #pragma unroll
        for (int k = 0; k < 4; k++) {
            int idx = base + k * 256;
            if (idx < n4) out[idx] = v;
        }
    }
}

// K3: pure scatter — one coalesced 8B load, one random 4B store.
// PDL: launches early, waits for the whole K2 grid (fill + vals) to complete.
__global__ void __launch_bounds__(256)
k3_scatter(float* __restrict__ out, int E) {
    pdl_wait();
    const int e = blockIdx.x * blockDim.x + threadIdx.x;
    if (e < E) {
        const uint2 p = g_pack[e];
        out[p.x] = __uint_as_float(p.y);
    }
}

extern "C" void kernel_launch(void* const* d_in, const int* in_sizes, int n_in,
                              void* d_out, int out_size) {
    const float* h       = (const float*)d_in[0];
    const int*   sources = (const int*)d_in[1];
    const int*   dests   = (const int*)d_in[2];
    const float* weights = (const float*)d_in[3];
    const float* W       = (const float*)d_in[4];
    const float* b       = (const float*)d_in[5];
    float* out = (float*)d_out;

    int N = in_sizes[0] / HDIM;     // 12288
    int E = in_sizes[1];            // 393216

    long long total = (long long)N * N;
    int n4 = (int)(total >> 2);     // 37,748,736
    const int nFillBlks = (n4 + 1023) / 1024;   // 36,864

    k2_fused<<<SIDE_BLKS + nFillBlks, 256>>>(h, sources, dests, weights, W, b,
                                             (float4*)out, N, E, n4);

    {
        cudaLaunchConfig_t cfg = {};
        cfg.gridDim = dim3((E + 255) / 256);
        cfg.blockDim = dim3(256);
        cfg.dynamicSmemBytes = 0;
        cfg.stream = 0;
        cudaLaunchAttribute attr[1];
        attr[0].id = cudaLaunchAttributeProgrammaticStreamSerialization;
        attr[0].val.programmaticStreamSerializationAllowed = 1;
        cfg.attrs = attr;
        cfg.numAttrs = 1;
        void* args[] = { (void*)&out, (void*)&E };
        cudaLaunchKernelExC(&cfg, (void*)k3_scatter, args);
    }
}